// round 6
// baseline (speedup 1.0000x reference)
#include <cuda_runtime.h>
#include <stdint.h>

#define BATCH 128
#define NANCH 16800
#define NQ (NANCH / 4)            // 4200 float4 per row
#define NEG_RATIO 3
#define SCALE_XY 10.0f
#define SCALE_WH 5.0f
#define T 1024
#define NW (T / 32)               // 32 warps
#define NIT ((NQ + T - 1) / T)    // 5
#define NBINS 17408               // float_bits >> 16, covers values < 512
#define CHB (NBINS / T)           // 17 bins per thread
#define FLT_EPS_ 1.1920929e-07f

// Cross-block scratch (allocation-free rule: __device__ globals)
__device__ float g_row_lossb[BATCH];
__device__ float g_row_lossl[BATCH];
__device__ int   g_row_posn[BATCH];
__device__ int   g_done = 0;

extern __shared__ unsigned s_dyn[];  // [NBINS] count | [NBINS] fsum

__device__ __forceinline__ float warp_sum(float v) {
    #pragma unroll
    for (int o = 16; o > 0; o >>= 1) v += __shfl_down_sync(0xFFFFFFFFu, v, o);
    return v;
}
__device__ __forceinline__ int warp_sum_i(int v) {
    #pragma unroll
    for (int o = 16; o > 0; o >>= 1) v += __shfl_down_sync(0xFFFFFFFFu, v, o);
    return v;
}
// suffix-inclusive scan within warp: result(lane) = sum over lanes >= lane
__device__ __forceinline__ int warp_suffix_incl_i(int v, int lane) {
    #pragma unroll
    for (int o = 1; o < 32; o <<= 1) {
        int u = __shfl_down_sync(0xFFFFFFFFu, v, o);
        if (lane + o < 32) v += u;
    }
    return v;
}
__device__ __forceinline__ float warp_suffix_incl_f(float v, int lane) {
    #pragma unroll
    for (int o = 1; o < 32; o <<= 1) {
        float u = __shfl_down_sync(0xFFFFFFFFu, v, o);
        if (lane + o < 32) v += u;
    }
    return v;
}

__global__ __launch_bounds__(T, 1)
void od_fused(const float* __restrict__ pbboxs,
              const float* __restrict__ plabels,
              const float* __restrict__ gbboxs,
              const float* __restrict__ glabels,
              const float* __restrict__ ancs,
              float* __restrict__ out, int out_size) {
    const int b    = blockIdx.x;
    const int tid  = threadIdx.x;
    const int lane = tid & 31;
    const int wid  = tid >> 5;

    int*   s_cnt_h  = (int*)s_dyn;
    float* s_fsum_h = (float*)(s_dyn + NBINS);

    __shared__ float s_sl1, s_bce, s_top;
    __shared__ int   s_cnt, s_last;
    __shared__ int   s_wtot[NW], s_wsuf[NW];
    __shared__ float s_ftot[NW], s_fsuf[NW];
    __shared__ float s_red[NW * 3];

    // ---- init ----
    #pragma unroll
    for (int j = 0; j < CHB; j++) {
        s_cnt_h[tid + j * T]  = 0;
        s_fsum_h[tid + j * T] = 0.f;
    }
    if (tid == 0) { s_sl1 = 0.f; s_bce = 0.f; s_top = 0.f; s_cnt = 0; }
    __syncthreads();

    const float4* pl4 = (const float4*)(plabels + (size_t)b * NANCH);
    const float4* gl4 = (const float4*)(glabels + (size_t)b * NANCH);
    const float4* pb  = (const float4*)pbboxs + (size_t)b * NANCH;
    const float4* gb  = (const float4*)gbboxs + (size_t)b * NANCH;
    const float4* an  = (const float4*)ancs;

    // ---- Single data pass: BCE + positive SmoothL1 + count/sum histogram ----
    float acc_sl1 = 0.f, acc_bce = 0.f;
    int cnt = 0;
    #pragma unroll
    for (int it = 0; it < NIT; it++) {
        const int i4 = tid + it * T;
        if (i4 < NQ) {
            float4 xv = pl4[i4];
            float4 yv = gl4[i4];
            #pragma unroll
            for (int c = 0; c < 4; c++) {
                float x = (c == 0) ? xv.x : (c == 1) ? xv.y : (c == 2) ? xv.z : xv.w;
                float y = (c == 0) ? yv.x : (c == 1) ? yv.y : (c == 2) ? yv.z : yv.w;
                float bce = fmaxf(x, 0.f) - x * y + __logf(1.f + __expf(-fabsf(x)));
                if (y > 0.f) {
                    const int i = 4 * i4 + c;
                    float4 p = pb[i];
                    float4 g = gb[i];
                    float4 a = an[i];
                    float inv_az = 1.f / a.z;
                    float inv_aw = 1.f / a.w;
                    float d0 = p.x - SCALE_XY * (g.x - a.x) * inv_az;
                    float d1 = p.y - SCALE_XY * (g.y - a.y) * inv_aw;
                    float d2 = p.z - SCALE_WH * __logf(g.z * inv_az);
                    float d3 = p.w - SCALE_WH * __logf(g.w * inv_aw);
                    float sl1 = 0.f, ad;
                    ad = fabsf(d0); sl1 += (ad < 1.f) ? 0.5f * d0 * d0 : ad - 0.5f;
                    ad = fabsf(d1); sl1 += (ad < 1.f) ? 0.5f * d1 * d1 : ad - 0.5f;
                    ad = fabsf(d2); sl1 += (ad < 1.f) ? 0.5f * d2 * d2 : ad - 0.5f;
                    ad = fabsf(d3); sl1 += (ad < 1.f) ? 0.5f * d3 * d3 : ad - 0.5f;
                    acc_sl1 += sl1;
                    acc_bce += bce;
                    cnt++;
                    // positives excluded from negative mining: counted in bin 0
                    atomicAdd(&s_cnt_h[0], 1);
                } else {
                    unsigned bin = __float_as_uint(bce) >> 16;  // bce >= 0
                    bin = min(bin, (unsigned)(NBINS - 1));
                    atomicAdd(&s_cnt_h[bin], 1);
                    atomicAdd(&s_fsum_h[bin], bce);
                }
            }
        }
    }
    {
        float w1 = warp_sum(acc_sl1);
        float w2 = warp_sum(acc_bce);
        int   w3 = warp_sum_i(cnt);
        if (lane == 0) {
            if (w1 != 0.f) atomicAdd(&s_sl1, w1);
            if (w2 != 0.f) atomicAdd(&s_bce, w2);
            if (w3 != 0)   atomicAdd(&s_cnt, w3);
        }
    }
    __syncthreads();

    const int pos_num = s_cnt;
    int K = NEG_RATIO * pos_num;
    if (K > NANCH) K = NANCH;

    if (K > 0) {
        // ---- Cooperative suffix-scan over NBINS (counts + float sums) ----
        const int base = tid * CHB;
        int   tot = 0;
        float ftot = 0.f;
        int   lc[CHB];
        float lf[CHB];
        #pragma unroll
        for (int j = 0; j < CHB; j++) {
            lc[j] = s_cnt_h[base + j];
            lf[j] = s_fsum_h[base + j];
            tot  += lc[j];
            ftot += lf[j];
        }
        int   incl  = warp_suffix_incl_i(tot, lane);
        float fincl = warp_suffix_incl_f(ftot, lane);
        if (lane == 0) { s_wtot[wid] = incl; s_ftot[wid] = fincl; }
        __syncthreads();
        if (tid < 32) {
            int   wv = s_wtot[lane];
            float fv = s_ftot[lane];
            int   wi = warp_suffix_incl_i(wv, lane);
            float fi = warp_suffix_incl_f(fv, lane);
            s_wsuf[lane] = wi - wv;   // counts strictly above this warp
            s_fsuf[lane] = fi - fv;   // float sum strictly above this warp
        }
        __syncthreads();
        const int   excl  = (incl - tot) + s_wsuf[wid];
        const float fexcl = (fincl - ftot) + s_fsuf[wid];

        if (excl < K && excl + tot >= K) {
            // this thread's chunk contains the threshold bin
            int   cum  = excl;
            float fcum = fexcl;
            #pragma unroll
            for (int j = CHB - 1; j >= 0; j--) {
                const int h = lc[j];
                cum += h;
                if (cum >= K) {
                    const int   kr  = K - (cum - h);
                    const float avg = lf[j] / (float)(h > 0 ? h : 1);
                    s_top = fcum + (float)kr * avg;  // exact above-sum + tie avg
                    break;
                }
                fcum += lf[j];
            }
        }
        __syncthreads();
    }
    const float sum_top = (K > 0) ? s_top : 0.f;

    // ---- Publish row; last block does the final reduction ----
    if (tid == 0) {
        g_row_posn[b]  = pos_num;
        g_row_lossb[b] = s_sl1;
        g_row_lossl[b] = s_bce + sum_top;
        __threadfence();
        int prev = atomicAdd(&g_done, 1);
        s_last = (prev == BATCH - 1);
    }
    __syncthreads();

    if (s_last) {
        float vlb = 0.f, vll = 0.f, vm = 0.f;
        if (tid < BATCH) {
            float pn  = (float)((volatile int*)g_row_posn)[tid];
            float lbv = ((volatile float*)g_row_lossb)[tid];
            float llv = ((volatile float*)g_row_lossl)[tid];
            float mask = (pn > 0.f) ? 1.f : 0.f;
            float wgt  = mask / fmaxf(pn, FLT_EPS_);
            vlb = lbv * wgt;
            vll = llv * wgt;
            vm  = wgt;
        }
        vlb = warp_sum(vlb);
        vll = warp_sum(vll);
        vm  = warp_sum(vm);
        if (lane == 0) {
            s_red[wid * 3 + 0] = vlb;
            s_red[wid * 3 + 1] = vll;
            s_red[wid * 3 + 2] = vm;
        }
        __syncthreads();
        if (tid == 0) {
            float slb = 0.f, sll = 0.f, sm = 0.f;
            #pragma unroll
            for (int w = 0; w < NW; w++) {
                slb += s_red[w * 3 + 0];
                sll += s_red[w * 3 + 1];
                sm  += s_red[w * 3 + 2];
            }
            const float lb = slb / (float)BATCH;
            const float ll = sll / (float)BATCH;
            const float total = (lb + ll) * (sm / (float)BATCH);
            if (out_size >= 1) out[0] = total;
            if (out_size >= 2) out[1] = lb;
            if (out_size >= 3) out[2] = ll;
            g_done = 0;  // reset for next graph replay
        }
    }
}

extern "C" void kernel_launch(void* const* d_in, const int* in_sizes, int n_in,
                              void* d_out, int out_size) {
    const float* pbboxs  = (const float*)d_in[0];
    const float* plabels = (const float*)d_in[1];
    const float* gbboxs  = (const float*)d_in[2];
    const float* glabels = (const float*)d_in[3];
    const float* ancs    = (const float*)d_in[4];
    (void)in_sizes; (void)n_in;

    const size_t smem = (size_t)NBINS * 2 * sizeof(unsigned);  // ~139 KB
    cudaFuncSetAttribute(od_fused,
                         cudaFuncAttributeMaxDynamicSharedMemorySize, (int)smem);

    od_fused<<<BATCH, T, smem>>>(pbboxs, plabels, gbboxs, glabels, ancs,
                                 (float*)d_out, out_size);
}